// round 1
// baseline (speedup 1.0000x reference)
#include <cuda_runtime.h>
#include <math.h>

#define B_SZ     2
#define L_SEQ    2048
#define D_MODEL  1024
#define D_INNER  2048
#define D_STATE  16
#define DT_RANK  64
#define NROWS    (B_SZ * L_SEQ)          // 4096
#define XDBL_W   (DT_RANK + 2 * D_STATE) // 96

// ---------------- scratch (device globals; no allocs allowed) ----------------
__device__ float g_xz  [(size_t)NROWS * 2 * D_INNER]; // 4096 x 4096
__device__ float g_uc  [(size_t)NROWS * D_INNER];     // 4096 x 2048
__device__ float g_xdbl[(size_t)NROWS * XDBL_W];      // 4096 x 96
__device__ float g_dt  [(size_t)NROWS * D_INNER];     // 4096 x 2048
__device__ float g_y   [(size_t)NROWS * D_INNER];     // 4096 x 2048
__device__ float g_o   [(size_t)NROWS * D_MODEL];     // 4096 x 1024

// ---------------- generic NT GEMM: C[m,n] = sum_k A[m,k]*B[n,k] ----------------
// MODE 0: plain   MODE 1: softplus(acc + bias[n])
template <int MODE>
__global__ void __launch_bounds__(256)
gemm_nt(const float* __restrict__ A, const float* __restrict__ Bm,
        float* __restrict__ C, int N, int K,
        int lda, int ldb, int ldc, const float* __restrict__ bias)
{
    constexpr int BM = 128, BN = 64, BK = 16;
    __shared__ float As[BK][BM + 4];
    __shared__ float Bs[BK][BN + 4];

    const int tid = threadIdx.x;
    const int tx  = tid & 15;   // n direction (4 cols each)
    const int ty  = tid >> 4;   // m direction (8 rows each)
    const int m0  = blockIdx.y * BM;
    const int n0  = blockIdx.x * BN;

    float acc[8][4];
#pragma unroll
    for (int i = 0; i < 8; i++)
#pragma unroll
        for (int j = 0; j < 4; j++) acc[i][j] = 0.f;

    const int ar = tid >> 2;        // 0..63
    const int ac = (tid & 3) * 4;   // 0,4,8,12

    for (int k0 = 0; k0 < K; k0 += BK) {
        // A tile: 128x16, two passes of 64 rows, float4 along K, store transposed
#pragma unroll
        for (int p = 0; p < 2; p++) {
            int r = p * 64 + ar;
            float4 v = *(const float4*)(A + (size_t)(m0 + r) * lda + k0 + ac);
            As[ac + 0][r] = v.x; As[ac + 1][r] = v.y;
            As[ac + 2][r] = v.z; As[ac + 3][r] = v.w;
        }
        // B tile: 64x16 (guard rows vs N for the N=96 call)
        {
            int r = ar;
            int gn = n0 + r;
            float4 v = make_float4(0.f, 0.f, 0.f, 0.f);
            if (gn < N) v = *(const float4*)(Bm + (size_t)gn * ldb + k0 + ac);
            Bs[ac + 0][r] = v.x; Bs[ac + 1][r] = v.y;
            Bs[ac + 2][r] = v.z; Bs[ac + 3][r] = v.w;
        }
        __syncthreads();

#pragma unroll
        for (int kk = 0; kk < BK; kk++) {
            float4 a0 = *(const float4*)&As[kk][ty * 8];
            float4 a1 = *(const float4*)&As[kk][ty * 8 + 4];
            float4 bv = *(const float4*)&Bs[kk][tx * 4];
            float av[8] = {a0.x, a0.y, a0.z, a0.w, a1.x, a1.y, a1.z, a1.w};
            float bb[4] = {bv.x, bv.y, bv.z, bv.w};
#pragma unroll
            for (int i = 0; i < 8; i++)
#pragma unroll
                for (int j = 0; j < 4; j++) acc[i][j] += av[i] * bb[j];
        }
        __syncthreads();
    }

#pragma unroll
    for (int i = 0; i < 8; i++) {
        int m = m0 + ty * 8 + i;
#pragma unroll
        for (int j = 0; j < 4; j++) {
            int n = n0 + tx * 4 + j;
            if (n < N) {
                float v = acc[i][j];
                if (MODE == 1) {
                    v += bias[n];
                    v = (v > 20.f) ? v : log1pf(__expf(v));
                }
                C[(size_t)m * ldc + n] = v;
            }
        }
    }
}

// ---------------- depthwise causal conv (k=4) + bias + SiLU ----------------
__global__ void __launch_bounds__(256)
conv_silu_kernel(const float* __restrict__ conv_w, const float* __restrict__ conv_b)
{
    int idx = blockIdx.x * blockDim.x + threadIdx.x;
    if (idx >= NROWS * D_INNER) return;
    int d = idx & (D_INNER - 1);
    int m = idx >> 11;          // row = b*L + t
    int t = m & (L_SEQ - 1);

    float acc = conv_b[d];
#pragma unroll
    for (int j = 0; j < 4; j++) {
        int tt = t - 3 + j;
        if (tt >= 0)
            acc += g_xz[(size_t)(m - 3 + j) * (2 * D_INNER) + d] * conv_w[d * 4 + j];
    }
    float s = acc / (1.f + __expf(-acc));   // silu
    g_uc[(size_t)m * D_INNER + d] = s;
}

// ---------------- selective scan (fused +u*D and *silu(z)) ----------------
// 128 blocks x 128 threads. thread -> (channel = c0 + tid/4, state group g = tid%4)
__global__ void __launch_bounds__(128)
scan_kernel(const float* __restrict__ A_log, const float* __restrict__ Dw)
{
    const int blk = blockIdx.x;
    const int b   = blk >> 6;            // 64 blocks per batch
    const int c0  = (blk & 63) * 32;
    const int tid = threadIdx.x;
    const int c   = c0 + (tid >> 2);
    const int g   = tid & 3;

    const float A0 = -__expf(A_log[c * D_STATE + g * 4 + 0]);
    const float A1 = -__expf(A_log[c * D_STATE + g * 4 + 1]);
    const float A2 = -__expf(A_log[c * D_STATE + g * 4 + 2]);
    const float A3 = -__expf(A_log[c * D_STATE + g * 4 + 3]);
    const float Dc = Dw[c];

    float h0 = 0.f, h1 = 0.f, h2 = 0.f, h3 = 0.f;

    const size_t rbase = (size_t)b * L_SEQ;
    const float* dt_p = g_dt   + rbase * D_INNER + c;
    const float* uc_p = g_uc   + rbase * D_INNER + c;
    const float* xd_p = g_xdbl + rbase * XDBL_W;
    const float* z_p  = g_xz   + rbase * (2 * D_INNER) + D_INNER + c;
    float*       y_p  = g_y    + rbase * D_INNER + c;

    for (int t = 0; t < L_SEQ; t++) {
        float  dtv = dt_p[(size_t)t * D_INNER];
        float  uv  = uc_p[(size_t)t * D_INNER];
        float4 Bv  = *(const float4*)(xd_p + (size_t)t * XDBL_W + DT_RANK + g * 4);
        float4 Cv  = *(const float4*)(xd_p + (size_t)t * XDBL_W + DT_RANK + D_STATE + g * 4);

        float du = dtv * uv;
        h0 = h0 * __expf(dtv * A0) + du * Bv.x;
        h1 = h1 * __expf(dtv * A1) + du * Bv.y;
        h2 = h2 * __expf(dtv * A2) + du * Bv.z;
        h3 = h3 * __expf(dtv * A3) + du * Bv.w;

        float p = h0 * Cv.x + h1 * Cv.y + h2 * Cv.z + h3 * Cv.w;
        p += __shfl_xor_sync(0xffffffffu, p, 1);
        p += __shfl_xor_sync(0xffffffffu, p, 2);

        if (g == 0) {
            float zv = z_p[(size_t)t * (2 * D_INNER)];
            float sz = zv / (1.f + __expf(-zv));
            y_p[(size_t)t * D_INNER] = (p + uv * Dc) * sz;
        }
    }
}

// ---------------- residual + LayerNorm ----------------
__global__ void __launch_bounds__(256)
ln_kernel(const float* __restrict__ x, const float* __restrict__ w,
          const float* __restrict__ b, float* __restrict__ out)
{
    __shared__ float red[8];
    const int m   = blockIdx.x;
    const int tid = threadIdx.x;

    float4 v  = *(const float4*)(g_o + (size_t)m * D_MODEL + tid * 4);
    float4 xr = *(const float4*)(x   + (size_t)m * D_MODEL + tid * 4);
    v.x += xr.x; v.y += xr.y; v.z += xr.z; v.w += xr.w;

    float s = v.x + v.y + v.z + v.w;
#pragma unroll
    for (int o = 16; o; o >>= 1) s += __shfl_xor_sync(0xffffffffu, s, o);
    if ((tid & 31) == 0) red[tid >> 5] = s;
    __syncthreads();
    float tot = 0.f;
#pragma unroll
    for (int i = 0; i < 8; i++) tot += red[i];
    const float mu = tot * (1.f / (float)D_MODEL);
    __syncthreads();

    float d0 = v.x - mu, d1 = v.y - mu, d2 = v.z - mu, d3 = v.w - mu;
    float sq = d0 * d0 + d1 * d1 + d2 * d2 + d3 * d3;
#pragma unroll
    for (int o = 16; o; o >>= 1) sq += __shfl_xor_sync(0xffffffffu, sq, o);
    if ((tid & 31) == 0) red[tid >> 5] = sq;
    __syncthreads();
    float tot2 = 0.f;
#pragma unroll
    for (int i = 0; i < 8; i++) tot2 += red[i];
    const float rs = rsqrtf(tot2 * (1.f / (float)D_MODEL) + 1e-5f);

    float4 wv = *(const float4*)(w + tid * 4);
    float4 bv = *(const float4*)(b + tid * 4);
    float4 o4;
    o4.x = d0 * rs * wv.x + bv.x;
    o4.y = d1 * rs * wv.y + bv.y;
    o4.z = d2 * rs * wv.z + bv.z;
    o4.w = d3 * rs * wv.w + bv.w;
    *(float4*)(out + (size_t)m * D_MODEL + tid * 4) = o4;
}

// ---------------- launch ----------------
extern "C" void kernel_launch(void* const* d_in, const int* in_sizes, int n_in,
                              void* d_out, int out_size)
{
    const float* x          = (const float*)d_in[0];
    const float* in_proj_w  = (const float*)d_in[1];
    const float* conv_w     = (const float*)d_in[2];
    const float* conv_b     = (const float*)d_in[3];
    const float* x_proj_w   = (const float*)d_in[4];
    const float* dt_proj_w  = (const float*)d_in[5];
    const float* dt_proj_b  = (const float*)d_in[6];
    const float* A_log      = (const float*)d_in[7];
    const float* Dw         = (const float*)d_in[8];
    const float* out_proj_w = (const float*)d_in[9];
    const float* ln_w       = (const float*)d_in[10];
    const float* ln_b       = (const float*)d_in[11];
    float* out = (float*)d_out;

    float *p_xz, *p_uc, *p_xdbl, *p_dt, *p_y, *p_o;
    cudaGetSymbolAddress((void**)&p_xz,   g_xz);
    cudaGetSymbolAddress((void**)&p_uc,   g_uc);
    cudaGetSymbolAddress((void**)&p_xdbl, g_xdbl);
    cudaGetSymbolAddress((void**)&p_dt,   g_dt);
    cudaGetSymbolAddress((void**)&p_y,    g_y);
    cudaGetSymbolAddress((void**)&p_o,    g_o);

    // 1) xz = x @ in_proj_w.T        (4096 x 4096, K=1024)
    gemm_nt<0><<<dim3(4096 / 64, 4096 / 128), 256>>>(
        x, in_proj_w, p_xz, 2 * D_INNER, D_MODEL, D_MODEL, D_MODEL, 2 * D_INNER, nullptr);

    // 2) u_c = silu(depthwise_conv(u) + b)
    conv_silu_kernel<<<(NROWS * D_INNER) / 256, 256>>>(conv_w, conv_b);

    // 3) x_dbl = u_c @ x_proj_w.T    (4096 x 96, K=2048)
    gemm_nt<0><<<dim3(2, 4096 / 128), 256>>>(
        p_uc, x_proj_w, p_xdbl, XDBL_W, D_INNER, D_INNER, D_INNER, XDBL_W, nullptr);

    // 4) dt = softplus(dt_lr @ dt_proj_w.T + dt_proj_b)  (4096 x 2048, K=64, lda=96)
    gemm_nt<1><<<dim3(D_INNER / 64, 4096 / 128), 256>>>(
        p_xdbl, dt_proj_w, p_dt, D_INNER, DT_RANK, XDBL_W, DT_RANK, D_INNER, dt_proj_b);

    // 5) selective scan + (y + u*D)*silu(z)
    scan_kernel<<<128, 128>>>(A_log, Dw);

    // 6) o = y @ out_proj_w.T        (4096 x 1024, K=2048)
    gemm_nt<0><<<dim3(D_MODEL / 64, 4096 / 128), 256>>>(
        p_y, out_proj_w, p_o, D_MODEL, D_INNER, D_INNER, D_INNER, D_MODEL, nullptr);

    // 7) out = LayerNorm(o + x)
    ln_kernel<<<NROWS, 256>>>(x, ln_w, ln_b, out);
}

// round 2
// speedup vs baseline: 1.2993x; 1.2993x over previous
#include <cuda_runtime.h>
#include <math.h>

#define B_SZ     2
#define L_SEQ    2048
#define D_MODEL  1024
#define D_INNER  2048
#define D_STATE  16
#define DT_RANK  64
#define NROWS    (B_SZ * L_SEQ)          // 4096
#define XDBL_W   (DT_RANK + 2 * D_STATE) // 96

// ---------------- scratch (device globals; no allocs allowed) ----------------
__device__ float g_xz  [(size_t)NROWS * 2 * D_INNER]; // 4096 x 4096
__device__ float g_uc  [(size_t)NROWS * D_INNER];     // 4096 x 2048
__device__ float g_xdbl[(size_t)NROWS * XDBL_W];      // 4096 x 96
__device__ float g_dt  [(size_t)NROWS * D_INNER];     // 4096 x 2048
__device__ float g_y   [(size_t)NROWS * D_INNER];     // 4096 x 2048
__device__ float g_o   [(size_t)NROWS * D_MODEL];     // 4096 x 1024

__device__ __forceinline__ unsigned f2tf32(float f) {
    unsigned r;
    asm("cvt.rna.tf32.f32 %0, %1;" : "=r"(r) : "f"(f));
    return r;
}

__device__ __forceinline__ void mma_tf32(float c[4], unsigned a0, unsigned a1,
                                         unsigned a2, unsigned a3,
                                         unsigned b0, unsigned b1) {
    asm volatile(
        "mma.sync.aligned.m16n8k8.row.col.f32.tf32.tf32.f32 "
        "{%0,%1,%2,%3}, {%4,%5,%6,%7}, {%8,%9}, {%0,%1,%2,%3};"
        : "+f"(c[0]), "+f"(c[1]), "+f"(c[2]), "+f"(c[3])
        : "r"(a0), "r"(a1), "r"(a2), "r"(a3), "r"(b0), "r"(b1));
}

// ================= tf32 tensor-core NT GEMM =================
// C[m,n] = sum_k A[m,k] * B[n,k].   M = 4096 (multiple of 128).
// Block tile 128x64xK16, 256 threads = 8 warps (4 m-warps x 2 n-warps),
// warp tile 32x32 (2 m-frags x 4 n-frags of m16n8k8).
// Shared layout: k16 chunk stored permuted: element (r, k) with k = 4j+i goes
// to word  As[r][ (i ^ ((r>>1)&3))*4 + j ]  -> frag load = one LDS.128,
// conflict-free for both the scatter STS and the fragment LDS.
// MODE 0: plain    MODE 1: softplus(acc + bias[n])
template <int MODE>
__global__ void __launch_bounds__(256, 2)
gemm_tf32(const float* __restrict__ A, const float* __restrict__ Bm,
          float* __restrict__ C, int N, int K,
          int lda, int ldb, int ldc, const float* __restrict__ bias)
{
    __shared__ unsigned As[2][128][16];
    __shared__ unsigned Bs[2][64][16];

    const int tid    = threadIdx.x;
    const int warp   = tid >> 5;
    const int lane   = tid & 31;
    const int g      = lane >> 2;       // group id 0..7
    const int tg     = lane & 3;        // thread-in-group 0..3
    const int warp_m = warp & 3;        // 0..3  (32 rows each)
    const int warp_n = warp >> 2;       // 0..1  (32 cols each)
    const int m0     = blockIdx.y * 128;
    const int n0     = blockIdx.x * 64;

    // loader assignment
    const int rA0 = tid >> 2;           // 0..63
    const int rA1 = rA0 + 64;           // 64..127
    const int jA  = tid & 3;            // k4 group
    const int rB  = tid >> 2;
    const int jB  = tid & 3;
    const bool bOK = (n0 + rB) < N;

    const float* Arow0 = A  + (size_t)(m0 + rA0) * lda + 4 * jA;
    const float* Arow1 = A  + (size_t)(m0 + rA1) * lda + 4 * jA;
    const float* Brow  = bOK ? (Bm + (size_t)(n0 + rB) * ldb + 4 * jB) : nullptr;

    // swizzled store columns (i = vector component 0..3)
    const int swA0 = (rA0 >> 1) & 3, swA1 = (rA1 >> 1) & 3, swB = (rB >> 1) & 3;

    float acc[2][4][4];
#pragma unroll
    for (int i = 0; i < 2; i++)
#pragma unroll
        for (int j = 0; j < 4; j++)
#pragma unroll
            for (int c = 0; c < 4; c++) acc[i][j][c] = 0.f;

    const int nk = K >> 4;

    // prologue: stage chunk 0
    float4 va0 = *(const float4*)(Arow0);
    float4 va1 = *(const float4*)(Arow1);
    float4 vb  = bOK ? *(const float4*)(Brow) : make_float4(0.f, 0.f, 0.f, 0.f);
    {
        As[0][rA0][((0 ^ swA0) << 2) + jA] = f2tf32(va0.x);
        As[0][rA0][((1 ^ swA0) << 2) + jA] = f2tf32(va0.y);
        As[0][rA0][((2 ^ swA0) << 2) + jA] = f2tf32(va0.z);
        As[0][rA0][((3 ^ swA0) << 2) + jA] = f2tf32(va0.w);
        As[0][rA1][((0 ^ swA1) << 2) + jA] = f2tf32(va1.x);
        As[0][rA1][((1 ^ swA1) << 2) + jA] = f2tf32(va1.y);
        As[0][rA1][((2 ^ swA1) << 2) + jA] = f2tf32(va1.z);
        As[0][rA1][((3 ^ swA1) << 2) + jA] = f2tf32(va1.w);
        Bs[0][rB ][((0 ^ swB ) << 2) + jB] = f2tf32(vb.x);
        Bs[0][rB ][((1 ^ swB ) << 2) + jB] = f2tf32(vb.y);
        Bs[0][rB ][((2 ^ swB ) << 2) + jB] = f2tf32(vb.z);
        Bs[0][rB ][((3 ^ swB ) << 2) + jB] = f2tf32(vb.w);
    }
    __syncthreads();

    int buf = 0;
    for (int ki = 0; ki < nk; ki++) {
        const bool hasNext = (ki + 1) < nk;
        if (hasNext) {
            const int koff = (ki + 1) << 4;
            va0 = *(const float4*)(Arow0 + koff);
            va1 = *(const float4*)(Arow1 + koff);
            vb  = bOK ? *(const float4*)(Brow + koff) : make_float4(0.f, 0.f, 0.f, 0.f);
        }

        // fragment loads (one LDS.128 each, conflict-free)
        uint4 afrag[2][2];  // [mfrag][row g / g+8]
#pragma unroll
        for (int i = 0; i < 2; i++) {
            int r1 = warp_m * 32 + i * 16 + g;
            int r2 = r1 + 8;
            afrag[i][0] = *(const uint4*)&As[buf][r1][(tg ^ ((r1 >> 1) & 3)) << 2];
            afrag[i][1] = *(const uint4*)&As[buf][r2][(tg ^ ((r2 >> 1) & 3)) << 2];
        }
        uint4 bfrag[4];
#pragma unroll
        for (int j = 0; j < 4; j++) {
            int rn = warp_n * 32 + j * 8 + g;
            bfrag[j] = *(const uint4*)&Bs[buf][rn][(tg ^ ((rn >> 1) & 3)) << 2];
        }

#pragma unroll
        for (int i = 0; i < 2; i++) {
#pragma unroll
            for (int j = 0; j < 4; j++) {
                // k = 0..7
                mma_tf32(acc[i][j], afrag[i][0].x, afrag[i][1].x,
                                    afrag[i][0].y, afrag[i][1].y,
                                    bfrag[j].x, bfrag[j].y);
                // k = 8..15
                mma_tf32(acc[i][j], afrag[i][0].z, afrag[i][1].z,
                                    afrag[i][0].w, afrag[i][1].w,
                                    bfrag[j].z, bfrag[j].w);
            }
        }

        if (hasNext) {
            const int nb = buf ^ 1;
            As[nb][rA0][((0 ^ swA0) << 2) + jA] = f2tf32(va0.x);
            As[nb][rA0][((1 ^ swA0) << 2) + jA] = f2tf32(va0.y);
            As[nb][rA0][((2 ^ swA0) << 2) + jA] = f2tf32(va0.z);
            As[nb][rA0][((3 ^ swA0) << 2) + jA] = f2tf32(va0.w);
            As[nb][rA1][((0 ^ swA1) << 2) + jA] = f2tf32(va1.x);
            As[nb][rA1][((1 ^ swA1) << 2) + jA] = f2tf32(va1.y);
            As[nb][rA1][((2 ^ swA1) << 2) + jA] = f2tf32(va1.z);
            As[nb][rA1][((3 ^ swA1) << 2) + jA] = f2tf32(va1.w);
            Bs[nb][rB ][((0 ^ swB ) << 2) + jB] = f2tf32(vb.x);
            Bs[nb][rB ][((1 ^ swB ) << 2) + jB] = f2tf32(vb.y);
            Bs[nb][rB ][((2 ^ swB ) << 2) + jB] = f2tf32(vb.z);
            Bs[nb][rB ][((3 ^ swB ) << 2) + jB] = f2tf32(vb.w);
        }
        __syncthreads();
        buf ^= 1;
    }

    // epilogue
#pragma unroll
    for (int i = 0; i < 2; i++) {
        int mbase = m0 + warp_m * 32 + i * 16 + g;
#pragma unroll
        for (int j = 0; j < 4; j++) {
            int nbase = n0 + warp_n * 32 + j * 8 + 2 * tg;
#pragma unroll
            for (int c = 0; c < 4; c++) {
                int m = mbase + ((c >> 1) << 3);
                int n = nbase + (c & 1);
                if (n < N) {
                    float v = acc[i][j][c];
                    if (MODE == 1) {
                        v += bias[n];
                        v = (v > 20.f) ? v : log1pf(__expf(v));
                    }
                    C[(size_t)m * ldc + n] = v;
                }
            }
        }
    }
}

// ---------------- depthwise causal conv (k=4) + bias + SiLU ----------------
__global__ void __launch_bounds__(256)
conv_silu_kernel(const float* __restrict__ conv_w, const float* __restrict__ conv_b)
{
    int idx = blockIdx.x * blockDim.x + threadIdx.x;
    if (idx >= NROWS * D_INNER) return;
    int d = idx & (D_INNER - 1);
    int m = idx >> 11;          // row = b*L + t
    int t = m & (L_SEQ - 1);

    float acc = conv_b[d];
#pragma unroll
    for (int j = 0; j < 4; j++) {
        int tt = t - 3 + j;
        if (tt >= 0)
            acc += g_xz[(size_t)(m - 3 + j) * (2 * D_INNER) + d] * conv_w[d * 4 + j];
    }
    float s = acc / (1.f + __expf(-acc));   // silu
    g_uc[(size_t)m * D_INNER + d] = s;
}

// ---------------- selective scan (fused +u*D and *silu(z)) ----------------
__global__ void __launch_bounds__(128)
scan_kernel(const float* __restrict__ A_log, const float* __restrict__ Dw)
{
    const int blk = blockIdx.x;
    const int b   = blk >> 6;            // 64 blocks per batch
    const int c0  = (blk & 63) * 32;
    const int tid = threadIdx.x;
    const int c   = c0 + (tid >> 2);
    const int g   = tid & 3;

    const float A0 = -__expf(A_log[c * D_STATE + g * 4 + 0]);
    const float A1 = -__expf(A_log[c * D_STATE + g * 4 + 1]);
    const float A2 = -__expf(A_log[c * D_STATE + g * 4 + 2]);
    const float A3 = -__expf(A_log[c * D_STATE + g * 4 + 3]);
    const float Dc = Dw[c];

    float h0 = 0.f, h1 = 0.f, h2 = 0.f, h3 = 0.f;

    const size_t rbase = (size_t)b * L_SEQ;
    const float* dt_p = g_dt   + rbase * D_INNER + c;
    const float* uc_p = g_uc   + rbase * D_INNER + c;
    const float* xd_p = g_xdbl + rbase * XDBL_W;
    const float* z_p  = g_xz   + rbase * (2 * D_INNER) + D_INNER + c;
    float*       y_p  = g_y    + rbase * D_INNER + c;

    for (int t = 0; t < L_SEQ; t++) {
        float  dtv = dt_p[(size_t)t * D_INNER];
        float  uv  = uc_p[(size_t)t * D_INNER];
        float4 Bv  = *(const float4*)(xd_p + (size_t)t * XDBL_W + DT_RANK + g * 4);
        float4 Cv  = *(const float4*)(xd_p + (size_t)t * XDBL_W + DT_RANK + D_STATE + g * 4);

        float du = dtv * uv;
        h0 = h0 * __expf(dtv * A0) + du * Bv.x;
        h1 = h1 * __expf(dtv * A1) + du * Bv.y;
        h2 = h2 * __expf(dtv * A2) + du * Bv.z;
        h3 = h3 * __expf(dtv * A3) + du * Bv.w;

        float p = h0 * Cv.x + h1 * Cv.y + h2 * Cv.z + h3 * Cv.w;
        p += __shfl_xor_sync(0xffffffffu, p, 1);
        p += __shfl_xor_sync(0xffffffffu, p, 2);

        if (g == 0) {
            float zv = z_p[(size_t)t * (2 * D_INNER)];
            float sz = zv / (1.f + __expf(-zv));
            y_p[(size_t)t * D_INNER] = (p + uv * Dc) * sz;
        }
    }
}

// ---------------- residual + LayerNorm ----------------
__global__ void __launch_bounds__(256)
ln_kernel(const float* __restrict__ x, const float* __restrict__ w,
          const float* __restrict__ b, float* __restrict__ out)
{
    __shared__ float red[8];
    const int m   = blockIdx.x;
    const int tid = threadIdx.x;

    float4 v  = *(const float4*)(g_o + (size_t)m * D_MODEL + tid * 4);
    float4 xr = *(const float4*)(x   + (size_t)m * D_MODEL + tid * 4);
    v.x += xr.x; v.y += xr.y; v.z += xr.z; v.w += xr.w;

    float s = v.x + v.y + v.z + v.w;
#pragma unroll
    for (int o = 16; o; o >>= 1) s += __shfl_xor_sync(0xffffffffu, s, o);
    if ((tid & 31) == 0) red[tid >> 5] = s;
    __syncthreads();
    float tot = 0.f;
#pragma unroll
    for (int i = 0; i < 8; i++) tot += red[i];
    const float mu = tot * (1.f / (float)D_MODEL);
    __syncthreads();

    float d0 = v.x - mu, d1 = v.y - mu, d2 = v.z - mu, d3 = v.w - mu;
    float sq = d0 * d0 + d1 * d1 + d2 * d2 + d3 * d3;
#pragma unroll
    for (int o = 16; o; o >>= 1) sq += __shfl_xor_sync(0xffffffffu, sq, o);
    if ((tid & 31) == 0) red[tid >> 5] = sq;
    __syncthreads();
    float tot2 = 0.f;
#pragma unroll
    for (int i = 0; i < 8; i++) tot2 += red[i];
    const float rs = rsqrtf(tot2 * (1.f / (float)D_MODEL) + 1e-5f);

    float4 wv = *(const float4*)(w + tid * 4);
    float4 bv = *(const float4*)(b + tid * 4);
    float4 o4;
    o4.x = d0 * rs * wv.x + bv.x;
    o4.y = d1 * rs * wv.y + bv.y;
    o4.z = d2 * rs * wv.z + bv.z;
    o4.w = d3 * rs * wv.w + bv.w;
    *(float4*)(out + (size_t)m * D_MODEL + tid * 4) = o4;
}

// ---------------- launch ----------------
extern "C" void kernel_launch(void* const* d_in, const int* in_sizes, int n_in,
                              void* d_out, int out_size)
{
    const float* x          = (const float*)d_in[0];
    const float* in_proj_w  = (const float*)d_in[1];
    const float* conv_w     = (const float*)d_in[2];
    const float* conv_b     = (const float*)d_in[3];
    const float* x_proj_w   = (const float*)d_in[4];
    const float* dt_proj_w  = (const float*)d_in[5];
    const float* dt_proj_b  = (const float*)d_in[6];
    const float* A_log      = (const float*)d_in[7];
    const float* Dw         = (const float*)d_in[8];
    const float* out_proj_w = (const float*)d_in[9];
    const float* ln_w       = (const float*)d_in[10];
    const float* ln_b       = (const float*)d_in[11];
    float* out = (float*)d_out;

    float *p_xz, *p_uc, *p_xdbl, *p_dt, *p_y, *p_o;
    cudaGetSymbolAddress((void**)&p_xz,   g_xz);
    cudaGetSymbolAddress((void**)&p_uc,   g_uc);
    cudaGetSymbolAddress((void**)&p_xdbl, g_xdbl);
    cudaGetSymbolAddress((void**)&p_dt,   g_dt);
    cudaGetSymbolAddress((void**)&p_y,    g_y);
    cudaGetSymbolAddress((void**)&p_o,    g_o);

    // 1) xz = x @ in_proj_w.T        (4096 x 4096, K=1024)
    gemm_tf32<0><<<dim3(4096 / 64, 4096 / 128), 256>>>(
        x, in_proj_w, p_xz, 2 * D_INNER, D_MODEL, D_MODEL, D_MODEL, 2 * D_INNER, nullptr);

    // 2) u_c = silu(depthwise_conv(u) + b)
    conv_silu_kernel<<<(NROWS * D_INNER) / 256, 256>>>(conv_w, conv_b);

    // 3) x_dbl = u_c @ x_proj_w.T    (4096 x 96, K=2048)
    gemm_tf32<0><<<dim3(2, 4096 / 128), 256>>>(
        p_uc, x_proj_w, p_xdbl, XDBL_W, D_INNER, D_INNER, D_INNER, XDBL_W, nullptr);

    // 4) dt = softplus(dt_lr @ dt_proj_w.T + dt_proj_b)  (4096 x 2048, K=64, lda=96)
    gemm_tf32<1><<<dim3(D_INNER / 64, 4096 / 128), 256>>>(
        p_xdbl, dt_proj_w, p_dt, D_INNER, DT_RANK, XDBL_W, DT_RANK, D_INNER, dt_proj_b);

    // 5) selective scan + (y + u*D)*silu(z)
    scan_kernel<<<128, 128>>>(A_log, Dw);

    // 6) o = y @ out_proj_w.T        (4096 x 1024, K=2048)
    gemm_tf32<0><<<dim3(D_MODEL / 64, 4096 / 128), 256>>>(
        p_y, out_proj_w, p_o, D_MODEL, D_INNER, D_INNER, D_INNER, D_MODEL, nullptr);

    // 7) out = LayerNorm(o + x)
    ln_kernel<<<NROWS, 256>>>(x, ln_w, ln_b, out);
}